// round 3
// baseline (speedup 1.0000x reference)
#include <cuda_runtime.h>

#define TOK     16
#define DIM_    180
#define NHEADS  6
#define HD_     30
#define NWIN    65536
#define NROWS   (NWIN * TOK)        // 1048576
#define QKVN    (3 * DIM_)          // 540

// Scratch (allocation-free rule: __device__ globals). ~755 MB each.
__device__ float g_q[NROWS * DIM_];
__device__ float g_k[NROWS * DIM_];
__device__ float g_v[NROWS * DIM_];
__device__ float g_att[NROWS * DIM_];

// ---------------------------------------------------------------------------
// SGEMM: C = A[MxK] @ B[KxN] + bias[N]
// Block tile 128x64, BK=16, 256 threads, 8x4 microtile.
// If C1 != nullptr, output columns are split into 3 buffers of width splitN.
// ---------------------------------------------------------------------------
#define BM 128
#define BN 64
#define BK 16
#define ASTRIDE (BM + 4)   // padded to kill store bank conflicts, keeps 16B align

__global__ __launch_bounds__(256) void sgemm_kernel(
    const float* __restrict__ A, const float* __restrict__ B,
    const float* __restrict__ bias,
    float* __restrict__ C0, float* __restrict__ C1, float* __restrict__ C2,
    int M, int N, int K, int splitN)
{
    __shared__ float As[BK * ASTRIDE];   // As[k][m]
    __shared__ float Bs[BK * BN];        // Bs[k][n]

    const int tid = threadIdx.x;
    const int tx = tid & 15;       // N direction (16)
    const int ty = tid >> 4;       // M direction (16)
    const int mBase = blockIdx.y * BM;
    const int nBase = blockIdx.x * BN;

    float acc[8][4];
#pragma unroll
    for (int i = 0; i < 8; i++)
#pragma unroll
        for (int j = 0; j < 4; j++) acc[i][j] = 0.f;

    for (int k0 = 0; k0 < K; k0 += BK) {
        // --- load A tile: 128 rows x 16 cols = 512 float4, 2 per thread ---
#pragma unroll
        for (int i = 0; i < 2; i++) {
            int idx4 = tid + i * 256;          // 0..511
            int r  = idx4 >> 2;                // 0..127
            int c4 = (idx4 & 3) * 4;           // 0,4,8,12
            float4 va = make_float4(0.f, 0.f, 0.f, 0.f);
            if (k0 + c4 < K) {                 // K % 4 == 0 so full float4 valid
                va = *reinterpret_cast<const float4*>(
                    A + (size_t)(mBase + r) * K + k0 + c4);
            }
            As[(c4 + 0) * ASTRIDE + r] = va.x;
            As[(c4 + 1) * ASTRIDE + r] = va.y;
            As[(c4 + 2) * ASTRIDE + r] = va.z;
            As[(c4 + 3) * ASTRIDE + r] = va.w;
        }
        // --- load B tile: 16 x 64 = 1024, 4 per thread ---
#pragma unroll
        for (int i = 0; i < 4; i++) {
            int idx = tid + i * 256;
            int r = idx >> 6;                  // 0..15
            int c = idx & 63;
            int kk = k0 + r, nn = nBase + c;
            Bs[r * BN + c] = (kk < K && nn < N) ? B[(size_t)kk * N + nn] : 0.f;
        }
        __syncthreads();

#pragma unroll
        for (int k = 0; k < BK; k++) {
            float a[8], b[4];
            const float4 a0 = *reinterpret_cast<const float4*>(&As[k * ASTRIDE + ty * 8 + 0]);
            const float4 a1 = *reinterpret_cast<const float4*>(&As[k * ASTRIDE + ty * 8 + 4]);
            a[0] = a0.x; a[1] = a0.y; a[2] = a0.z; a[3] = a0.w;
            a[4] = a1.x; a[5] = a1.y; a[6] = a1.z; a[7] = a1.w;
            const float4 b0 = *reinterpret_cast<const float4*>(&Bs[k * BN + tx * 4]);
            b[0] = b0.x; b[1] = b0.y; b[2] = b0.z; b[3] = b0.w;
#pragma unroll
            for (int i = 0; i < 8; i++)
#pragma unroll
                for (int j = 0; j < 4; j++)
                    acc[i][j] = fmaf(a[i], b[j], acc[i][j]);
        }
        __syncthreads();
    }

    // --- epilogue ---
#pragma unroll
    for (int i = 0; i < 8; i++) {
        int row = mBase + ty * 8 + i;
#pragma unroll
        for (int j = 0; j < 4; j++) {
            int n = nBase + tx * 4 + j;
            if (n < N) {
                float val = acc[i][j] + bias[n];
                if (C1) {
                    int part = n / splitN;
                    int nc = n - part * splitN;
                    float* Cp = (part == 0) ? C0 : ((part == 1) ? C1 : C2);
                    Cp[(size_t)row * splitN + nc] = val;
                } else {
                    C0[(size_t)row * N + n] = val;
                }
            }
        }
    }
}

// ---------------------------------------------------------------------------
// Attention: one warp per (window, head). 4 warps per block (static smem).
// S = (q*scale) @ k^T + bias ; softmax ; O = P @ v  -> bnhd layout.
// ---------------------------------------------------------------------------
__global__ __launch_bounds__(128) void attn_kernel(
    const float* __restrict__ gq, const float* __restrict__ gk,
    const float* __restrict__ gv, const float* __restrict__ btab,
    const int* __restrict__ ridx, float* __restrict__ out)
{
    __shared__ float sbias[NHEADS * 256];    // [h][r][c]
    __shared__ float sqT[4][HD_ * TOK];      // q transposed: [d][n]
    __shared__ float sk[4][TOK * HD_];       // [n][d]
    __shared__ float sv[4][TOK * HD_];       // [n][d]
    __shared__ float sPT[4][TOK * TOK];      // P transposed: [c][r]

    const int tid = threadIdx.x;
    for (int i = tid; i < NHEADS * 256; i += 128) {
        int h = i >> 8, rc = i & 255;
        sbias[i] = btab[ridx[rc] * NHEADS + h];
    }
    __syncthreads();

    const int warp = tid >> 5, lane = tid & 31;
    const int task = blockIdx.x * 4 + warp;
    const int b = task / NHEADS;
    const int h = task - b * NHEADS;
    const float scale = 0.18257418583505537f;  // 30^-0.5

    float* q = sqT[warp];
    float* k = sk[warp];
    float* v = sv[warp];
    float* P = sPT[warp];

    const size_t base = (size_t)b * TOK * DIM_ + h * HD_;
    for (int i = lane; i < TOK * HD_; i += 32) {
        int n = i / HD_, d = i - n * HD_;
        size_t g = base + (size_t)n * DIM_ + d;
        q[d * TOK + n] = gq[g] * scale;
        k[i] = gk[g];
        v[i] = gv[g];
    }
    __syncwarp();

    // S: 2 lanes per row, 8 cols each
    const int r  = lane >> 1;
    const int cb = (lane & 1) * 8;
    float s[8];
#pragma unroll
    for (int c = 0; c < 8; c++) {
        float a = sbias[h * 256 + r * 16 + cb + c];
#pragma unroll
        for (int d = 0; d < HD_; d++)
            a = fmaf(q[d * TOK + r], k[(cb + c) * HD_ + d], a);
        s[c] = a;
    }
    // softmax over the 16-wide row (pair of lanes)
    float mx = s[0];
#pragma unroll
    for (int c = 1; c < 8; c++) mx = fmaxf(mx, s[c]);
    mx = fmaxf(mx, __shfl_xor_sync(0xffffffffu, mx, 1));
    float sum = 0.f;
#pragma unroll
    for (int c = 0; c < 8; c++) { s[c] = __expf(s[c] - mx); sum += s[c]; }
    sum += __shfl_xor_sync(0xffffffffu, sum, 1);
    const float inv = 1.f / sum;
#pragma unroll
    for (int c = 0; c < 8; c++) P[(cb + c) * TOK + r] = s[c] * inv;
    __syncwarp();

    // O = P @ v : 2 lanes per row, 15 cols each
    const int cb2 = (lane & 1) * 15;
    float o[15];
#pragma unroll
    for (int c = 0; c < 15; c++) o[c] = 0.f;
#pragma unroll
    for (int m = 0; m < TOK; m++) {
        float p = P[m * TOK + r];
#pragma unroll
        for (int c = 0; c < 15; c++)
            o[c] = fmaf(p, v[m * HD_ + cb2 + c], o[c]);
    }
    size_t ob = (size_t)b * TOK * DIM_ + (size_t)r * DIM_ + h * HD_ + cb2;
#pragma unroll
    for (int c = 0; c < 15; c++) out[ob + c] = o[c];
}

// ---------------------------------------------------------------------------
extern "C" void kernel_launch(void* const* d_in, const int* in_sizes, int n_in,
                              void* d_out, int out_size)
{
    const float*     x      = (const float*)d_in[0];
    const float*     w_qkv  = (const float*)d_in[1];
    const float*     b_qkv  = (const float*)d_in[2];
    const float*     w_proj = (const float*)d_in[3];
    const float*     b_proj = (const float*)d_in[4];
    const float*     btab   = (const float*)d_in[5];
    const int*       ridx   = (const int*)d_in[6];
    float*           out    = (float*)d_out;

    float *gq, *gk, *gv, *ga;
    cudaGetSymbolAddress((void**)&gq, g_q);
    cudaGetSymbolAddress((void**)&gk, g_k);
    cudaGetSymbolAddress((void**)&gv, g_v);
    cudaGetSymbolAddress((void**)&ga, g_att);

    // 1) qkv = x @ w_qkv + b_qkv, split into q/k/v buffers
    dim3 g1((QKVN + BN - 1) / BN, NROWS / BM);   // (9, 8192)
    sgemm_kernel<<<g1, 256>>>(x, w_qkv, b_qkv, gq, gk, gv,
                              NROWS, QKVN, DIM_, DIM_);

    // 2) windowed attention with relative-position bias
    attn_kernel<<<(NWIN * NHEADS) / 4, 128>>>(gq, gk, gv, btab, ridx, ga);

    // 3) out = att @ w_proj + b_proj
    dim3 g3((DIM_ + BN - 1) / BN, NROWS / BM);   // (3, 8192)
    sgemm_kernel<<<g3, 256>>>(ga, w_proj, b_proj, out, nullptr, nullptr,
                              NROWS, DIM_, DIM_, 0);
}

// round 5
// speedup vs baseline: 1.1295x; 1.1295x over previous
#include <cuda_runtime.h>
#include <cuda_bf16.h>

#define TOK      16
#define DIM_     180
#define NHEADS   6
#define HD_      30
#define NWIN     65536
#define NROWS    (NWIN * TOK)       // 1048576
#define KPAD     192                // 180 padded to multiple of 32
#define NQKV     540
#define NQKV_PAD 576                // 9 * 64
#define NPROJ_PAD 192               // 3 * 64

// fp32 q/k/v for the attention kernel (~755 MB each)
__device__ float g_q[NROWS * DIM_];
__device__ float g_k[NROWS * DIM_];
__device__ float g_v[NROWS * DIM_];
// bf16 hi/lo split A operand, reused: x-split for GEMM1, attn output for GEMM3
__device__ __nv_bfloat16 g_ah[NROWS * KPAD];
__device__ __nv_bfloat16 g_al[NROWS * KPAD];
// split + padded weights
__device__ __nv_bfloat16 g_wqh[KPAD * NQKV_PAD];
__device__ __nv_bfloat16 g_wql[KPAD * NQKV_PAD];
__device__ __nv_bfloat16 g_wph[KPAD * NPROJ_PAD];
__device__ __nv_bfloat16 g_wpl[KPAD * NPROJ_PAD];

// ---------------------------------------------------------------------------
// PTX helpers
// ---------------------------------------------------------------------------
__device__ __forceinline__ void cp16(unsigned s, const void* g) {
    asm volatile("cp.async.cg.shared.global [%0], [%1], 16;" :: "r"(s), "l"(g));
}
__device__ __forceinline__ void cp_commit() {
    asm volatile("cp.async.commit_group;");
}
__device__ __forceinline__ void ldsm_x4(unsigned* r, unsigned addr) {
    asm volatile("ldmatrix.sync.aligned.m8n8.x4.shared.b16 {%0,%1,%2,%3}, [%4];"
                 : "=r"(r[0]), "=r"(r[1]), "=r"(r[2]), "=r"(r[3]) : "r"(addr));
}
__device__ __forceinline__ void ldsm_x4_t(unsigned* r, unsigned addr) {
    asm volatile("ldmatrix.sync.aligned.m8n8.x4.trans.shared.b16 {%0,%1,%2,%3}, [%4];"
                 : "=r"(r[0]), "=r"(r[1]), "=r"(r[2]), "=r"(r[3]) : "r"(addr));
}
__device__ __forceinline__ void mma_bf16(float* c, const unsigned* a, const unsigned* b) {
    asm volatile("mma.sync.aligned.m16n8k16.row.col.f32.bf16.bf16.f32 "
                 "{%0,%1,%2,%3}, {%4,%5,%6,%7}, {%8,%9}, {%0,%1,%2,%3};"
                 : "+f"(c[0]), "+f"(c[1]), "+f"(c[2]), "+f"(c[3])
                 : "r"(a[0]), "r"(a[1]), "r"(a[2]), "r"(a[3]), "r"(b[0]), "r"(b[1]));
}

// ---------------------------------------------------------------------------
// Split kernels: fp32 -> (hi bf16, lo bf16), zero-padded
// ---------------------------------------------------------------------------
__global__ void split_a_kernel(const float* __restrict__ src,
                               __nv_bfloat16* __restrict__ h,
                               __nv_bfloat16* __restrict__ l)
{
    int row = blockIdx.x;            // NROWS blocks, 192 threads
    int col = threadIdx.x;
    float v = (col < DIM_) ? src[(size_t)row * DIM_ + col] : 0.f;
    __nv_bfloat16 hv = __float2bfloat16(v);
    float r = v - __bfloat162float(hv);
    size_t o = (size_t)row * KPAD + col;
    h[o] = hv;
    l[o] = __float2bfloat16(r);
}

__global__ void split_w_kernel(const float* __restrict__ src, int rows, int cols,
                               __nv_bfloat16* __restrict__ h,
                               __nv_bfloat16* __restrict__ l, int padCols)
{
    int i = blockIdx.x * blockDim.x + threadIdx.x;   // KPAD * padCols elems
    if (i >= KPAD * padCols) return;
    int r = i / padCols, c = i - r * padCols;
    float v = (r < rows && c < cols) ? src[r * cols + c] : 0.f;
    __nv_bfloat16 hv = __float2bfloat16(v);
    h[i] = hv;
    l[i] = __float2bfloat16(v - __bfloat162float(hv));
}

// ---------------------------------------------------------------------------
// bf16x3 GEMM: C = Ah*Bh + Ah*Bl + Al*Bh + bias, fp32 accumulate.
// A: [M x KPAD] bf16 (lda=KPAD). B: [KPAD x Npad] bf16. 3 K-phases x 192.
// Tile 128x64, BK=32, 256 threads, warps 4(m) x 2(n), warp tile 32x32.
// If C1 != null: columns split into 3 outputs of width splitN (qkv).
// ---------------------------------------------------------------------------
#define GBM 128
#define GBN 64
#define GBK 32
#define ASTR 40       // bf16 units -> 80B row stride  (16B aligned, ldmatrix conflict-free)
#define BSTR 72       // bf16 units -> 144B row stride (16B aligned, ldmatrix conflict-free)
#define NCHUNK 18     // 3 phases * (192/32)

__global__ __launch_bounds__(256, 2) void gemm_bf16x3(
    const __nv_bfloat16* __restrict__ Ah, const __nv_bfloat16* __restrict__ Al,
    const __nv_bfloat16* __restrict__ Bh, const __nv_bfloat16* __restrict__ Bl,
    const float* __restrict__ bias,
    float* __restrict__ C0, float* __restrict__ C1, float* __restrict__ C2,
    int Npad, int Nreal, int splitN)
{
    __shared__ __nv_bfloat16 sA[2][GBM * ASTR];
    __shared__ __nv_bfloat16 sB[2][GBK * BSTR];

    const int tid  = threadIdx.x;
    const int lane = tid & 31;
    const int warp = tid >> 5;
    const int wm   = warp >> 1;          // 0..3 -> m offset *32
    const int wn   = warp & 1;           // 0..1 -> n offset *32
    const int mBase = blockIdx.y * GBM;
    const int nBase = blockIdx.x * GBN;

    float acc[2][4][4];
#pragma unroll
    for (int a = 0; a < 2; a++)
#pragma unroll
        for (int b = 0; b < 4; b++)
#pragma unroll
            for (int c = 0; c < 4; c++) acc[a][b][c] = 0.f;

    const unsigned aS0 = (unsigned)__cvta_generic_to_shared(&sA[0][0]);
    const unsigned aS1 = (unsigned)__cvta_generic_to_shared(&sA[1][0]);
    const unsigned bS0 = (unsigned)__cvta_generic_to_shared(&sB[0][0]);
    const unsigned bS1 = (unsigned)__cvta_generic_to_shared(&sB[1][0]);

    // ---- stage loader (no predicates: everything padded) ----
    auto loadStage = [&](int kIdx, int buf) {
        int p  = kIdx / 6;
        int kk = (kIdx - p * 6) * GBK;
        const __nv_bfloat16* Asrc = (p < 2) ? Ah : Al;
        const __nv_bfloat16* Bsrc = (p == 1) ? Bl : Bh;
        unsigned aS = buf ? aS1 : aS0;
        unsigned bS = buf ? bS1 : bS0;
        // A tile: 128 rows x 32 cols = 512 x 16B, 2 per thread
#pragma unroll
        for (int s = 0; s < 2; s++) {
            int q = tid + s * 256;
            int r = q >> 2, c = q & 3;
            cp16(aS + (unsigned)(r * ASTR + c * 8) * 2,
                 Asrc + (size_t)(mBase + r) * KPAD + kk + c * 8);
        }
        // B tile: 32 rows x 64 cols = 256 x 16B, 1 per thread
        {
            int r = tid >> 3, c = tid & 7;
            cp16(bS + (unsigned)(r * BSTR + c * 8) * 2,
                 Bsrc + (size_t)(kk + r) * Npad + nBase + c * 8);
        }
    };

    loadStage(0, 0);
    cp_commit();

    for (int kIdx = 0; kIdx < NCHUNK; kIdx++) {
        if (kIdx + 1 < NCHUNK) {
            loadStage(kIdx + 1, (kIdx + 1) & 1);
            cp_commit();
            asm volatile("cp.async.wait_group 1;");
        } else {
            asm volatile("cp.async.wait_group 0;");
        }
        __syncthreads();

        const int buf = kIdx & 1;
        const unsigned aS = buf ? aS1 : aS0;
        const unsigned bS = buf ? bS1 : bS0;
#pragma unroll
        for (int kf = 0; kf < 2; kf++) {
            unsigned ra[2][4], rb[2][4];
#pragma unroll
            for (int mf = 0; mf < 2; mf++) {
                unsigned addr = aS + (unsigned)((wm * 32 + mf * 16 + (lane & 15)) * ASTR
                                                + kf * 16 + (lane >> 4) * 8) * 2;
                ldsm_x4(ra[mf], addr);
            }
#pragma unroll
            for (int nf = 0; nf < 2; nf++) {
                unsigned addr = bS + (unsigned)((kf * 16 + (lane & 15)) * BSTR
                                                + wn * 32 + nf * 16 + (lane >> 4) * 8) * 2;
                ldsm_x4_t(rb[nf], addr);
            }
#pragma unroll
            for (int mf = 0; mf < 2; mf++)
#pragma unroll
                for (int nf = 0; nf < 2; nf++) {
                    mma_bf16(acc[mf][nf * 2 + 0], ra[mf], &rb[nf][0]);
                    mma_bf16(acc[mf][nf * 2 + 1], ra[mf], &rb[nf][2]);
                }
        }
        __syncthreads();
    }

    // ---- epilogue ----
#pragma unroll
    for (int mf = 0; mf < 2; mf++)
#pragma unroll
        for (int nf8 = 0; nf8 < 4; nf8++)
#pragma unroll
            for (int i = 0; i < 4; i++) {
                int row = mBase + wm * 32 + mf * 16 + (lane >> 2) + (i >> 1) * 8;
                int col = nBase + wn * 32 + nf8 * 8 + (lane & 3) * 2 + (i & 1);
                if (col < Nreal) {
                    float val = acc[mf][nf8][i] + bias[col];
                    if (C1) {
                        int part = col / splitN;
                        int nc = col - part * splitN;
                        float* Cp = (part == 0) ? C0 : ((part == 1) ? C1 : C2);
                        Cp[(size_t)row * splitN + nc] = val;
                    } else {
                        C0[(size_t)row * Nreal + col] = val;
                    }
                }
            }
}

// ---------------------------------------------------------------------------
// Attention: one warp per (window, head). Writes bf16 hi/lo split directly
// into g_ah/g_al (pad cols 180..191 stay zero from split_a).
// ---------------------------------------------------------------------------
__global__ __launch_bounds__(128) void attn_kernel(
    const float* __restrict__ gq, const float* __restrict__ gk,
    const float* __restrict__ gv, const float* __restrict__ btab,
    const int* __restrict__ ridx,
    __nv_bfloat16* __restrict__ outh, __nv_bfloat16* __restrict__ outl)
{
    __shared__ float sbias[NHEADS * 256];    // [h][r][c]
    __shared__ float sqT[4][HD_ * TOK];      // q transposed: [d][n]
    __shared__ float sk[4][TOK * HD_];       // [n][d]
    __shared__ float sv[4][TOK * HD_];       // [n][d]
    __shared__ float sPT[4][TOK * TOK];      // P transposed: [c][r]

    const int tid = threadIdx.x;
    for (int i = tid; i < NHEADS * 256; i += 128) {
        int h = i >> 8, rc = i & 255;
        sbias[i] = btab[ridx[rc] * NHEADS + h];
    }
    __syncthreads();

    const int warp = tid >> 5, lane = tid & 31;
    const int task = blockIdx.x * 4 + warp;
    const int b = task / NHEADS;
    const int h = task - b * NHEADS;
    const float scale = 0.18257418583505537f;  // 30^-0.5

    float* q = sqT[warp];
    float* k = sk[warp];
    float* v = sv[warp];
    float* P = sPT[warp];

    const size_t base = (size_t)b * TOK * DIM_ + h * HD_;
    for (int i = lane; i < TOK * HD_; i += 32) {
        int n = i / HD_, d = i - n * HD_;
        size_t g = base + (size_t)n * DIM_ + d;
        q[d * TOK + n] = gq[g] * scale;
        k[i] = gk[g];
        v[i] = gv[g];
    }
    __syncwarp();

    const int r  = lane >> 1;
    const int cb = (lane & 1) * 8;
    float s[8];
#pragma unroll
    for (int c = 0; c < 8; c++) {
        float a = sbias[h * 256 + r * 16 + cb + c];
#pragma unroll
        for (int d = 0; d < HD_; d++)
            a = fmaf(q[d * TOK + r], k[(cb + c) * HD_ + d], a);
        s[c] = a;
    }
    float mx = s[0];
#pragma unroll
    for (int c = 1; c < 8; c++) mx = fmaxf(mx, s[c]);
    mx = fmaxf(mx, __shfl_xor_sync(0xffffffffu, mx, 1));
    float sum = 0.f;
#pragma unroll
    for (int c = 0; c < 8; c++) { s[c] = __expf(s[c] - mx); sum += s[c]; }
    sum += __shfl_xor_sync(0xffffffffu, sum, 1);
    const float inv = 1.f / sum;
#pragma unroll
    for (int c = 0; c < 8; c++) P[(cb + c) * TOK + r] = s[c] * inv;
    __syncwarp();

    const int cb2 = (lane & 1) * 15;
    float o[15];
#pragma unroll
    for (int c = 0; c < 15; c++) o[c] = 0.f;
#pragma unroll
    for (int m = 0; m < TOK; m++) {
        float p = P[m * TOK + r];
#pragma unroll
        for (int c = 0; c < 15; c++)
            o[c] = fmaf(p, v[m * HD_ + cb2 + c], o[c]);
    }
    size_t ob = (size_t)b * TOK * KPAD + (size_t)r * KPAD + h * HD_ + cb2;
#pragma unroll
    for (int c = 0; c < 15; c++) {
        __nv_bfloat16 hv = __float2bfloat16(o[c]);
        outh[ob + c] = hv;
        outl[ob + c] = __float2bfloat16(o[c] - __bfloat162float(hv));
    }
}

// ---------------------------------------------------------------------------
extern "C" void kernel_launch(void* const* d_in, const int* in_sizes, int n_in,
                              void* d_out, int out_size)
{
    const float* x      = (const float*)d_in[0];
    const float* w_qkv  = (const float*)d_in[1];
    const float* b_qkv  = (const float*)d_in[2];
    const float* w_proj = (const float*)d_in[3];
    const float* b_proj = (const float*)d_in[4];
    const float* btab   = (const float*)d_in[5];
    const int*   ridx   = (const int*)d_in[6];
    float*       out    = (float*)d_out;

    float *gq, *gk, *gv;
    __nv_bfloat16 *ah, *al, *wqh, *wql, *wph, *wpl;
    cudaGetSymbolAddress((void**)&gq,  g_q);
    cudaGetSymbolAddress((void**)&gk,  g_k);
    cudaGetSymbolAddress((void**)&gv,  g_v);
    cudaGetSymbolAddress((void**)&ah,  g_ah);
    cudaGetSymbolAddress((void**)&al,  g_al);
    cudaGetSymbolAddress((void**)&wqh, g_wqh);
    cudaGetSymbolAddress((void**)&wql, g_wql);
    cudaGetSymbolAddress((void**)&wph, g_wph);
    cudaGetSymbolAddress((void**)&wpl, g_wpl);

    // 0) splits
    split_a_kernel<<<NROWS, KPAD>>>(x, ah, al);
    split_w_kernel<<<(KPAD * NQKV_PAD + 255) / 256, 256>>>(w_qkv, DIM_, NQKV, wqh, wql, NQKV_PAD);
    split_w_kernel<<<(KPAD * NPROJ_PAD + 255) / 256, 256>>>(w_proj, DIM_, DIM_, wph, wpl, NPROJ_PAD);

    // 1) qkv = x @ w_qkv + b_qkv  (bf16x3, split into q/k/v fp32)
    dim3 g1(NQKV_PAD / GBN, NROWS / GBM);    // (9, 8192)
    gemm_bf16x3<<<g1, 256>>>(ah, al, wqh, wql, b_qkv, gq, gk, gv,
                             NQKV_PAD, NQKV, DIM_);

    // 2) windowed attention; emits bf16 hi/lo into ah/al (pads still zero)
    attn_kernel<<<(NWIN * NHEADS) / 4, 128>>>(gq, gk, gv, btab, ridx, ah, al);

    // 3) out = att @ w_proj + b_proj  (bf16x3)
    dim3 g3(NPROJ_PAD / GBN, NROWS / GBM);   // (3, 8192)
    gemm_bf16x3<<<g3, 256>>>(ah, al, wph, wpl, b_proj, out, nullptr, nullptr,
                             NPROJ_PAD, DIM_, DIM_);
}

// round 6
// speedup vs baseline: 1.2479x; 1.1048x over previous
#include <cuda_runtime.h>
#include <cuda_bf16.h>

#define TOK      16
#define DIM_     180
#define NHEADS   6
#define HD_      30
#define NWIN     65536
#define NROWS    (NWIN * TOK)       // 1048576
#define KPAD     192                // 180 padded to multiple of 32
#define NQKV     540
#define NQKV_PAD 576                // 9 * 64
#define NPROJ_PAD 192               // 3 * 64

// fp32 q/k/v for the attention kernel (~755 MB each)
__device__ float g_q[NROWS * DIM_];
__device__ float g_k[NROWS * DIM_];
__device__ float g_v[NROWS * DIM_];
// bf16 hi/lo split A operand, reused: x-split for GEMM1, attn output for GEMM3
__device__ __nv_bfloat16 g_ah[NROWS * KPAD];
__device__ __nv_bfloat16 g_al[NROWS * KPAD];
// split + padded weights
__device__ __nv_bfloat16 g_wqh[KPAD * NQKV_PAD];
__device__ __nv_bfloat16 g_wql[KPAD * NQKV_PAD];
__device__ __nv_bfloat16 g_wph[KPAD * NPROJ_PAD];
__device__ __nv_bfloat16 g_wpl[KPAD * NPROJ_PAD];

// ---------------------------------------------------------------------------
// PTX helpers
// ---------------------------------------------------------------------------
__device__ __forceinline__ void cp16(unsigned s, const void* g) {
    asm volatile("cp.async.cg.shared.global [%0], [%1], 16;" :: "r"(s), "l"(g));
}
__device__ __forceinline__ void cp_commit() {
    asm volatile("cp.async.commit_group;");
}
__device__ __forceinline__ void ldsm_x4(unsigned* r, unsigned addr) {
    asm volatile("ldmatrix.sync.aligned.m8n8.x4.shared.b16 {%0,%1,%2,%3}, [%4];"
                 : "=r"(r[0]), "=r"(r[1]), "=r"(r[2]), "=r"(r[3]) : "r"(addr));
}
__device__ __forceinline__ void ldsm_x4_t(unsigned* r, unsigned addr) {
    asm volatile("ldmatrix.sync.aligned.m8n8.x4.trans.shared.b16 {%0,%1,%2,%3}, [%4];"
                 : "=r"(r[0]), "=r"(r[1]), "=r"(r[2]), "=r"(r[3]) : "r"(addr));
}
__device__ __forceinline__ void mma_bf16(float* c, const unsigned* a, const unsigned* b) {
    asm volatile("mma.sync.aligned.m16n8k16.row.col.f32.bf16.bf16.f32 "
                 "{%0,%1,%2,%3}, {%4,%5,%6,%7}, {%8,%9}, {%0,%1,%2,%3};"
                 : "+f"(c[0]), "+f"(c[1]), "+f"(c[2]), "+f"(c[3])
                 : "r"(a[0]), "r"(a[1]), "r"(a[2]), "r"(a[3]), "r"(b[0]), "r"(b[1]));
}

// ---------------------------------------------------------------------------
// Split kernels: fp32 -> (hi bf16, lo bf16), zero-padded
// ---------------------------------------------------------------------------
__global__ void split_a_kernel(const float* __restrict__ src,
                               __nv_bfloat16* __restrict__ h,
                               __nv_bfloat16* __restrict__ l)
{
    int row = blockIdx.x;            // NROWS blocks, 192 threads
    int col = threadIdx.x;
    float v = (col < DIM_) ? src[(size_t)row * DIM_ + col] : 0.f;
    __nv_bfloat16 hv = __float2bfloat16(v);
    float r = v - __bfloat162float(hv);
    size_t o = (size_t)row * KPAD + col;
    h[o] = hv;
    l[o] = __float2bfloat16(r);
}

__global__ void split_w_kernel(const float* __restrict__ src, int rows, int cols,
                               __nv_bfloat16* __restrict__ h,
                               __nv_bfloat16* __restrict__ l, int padCols)
{
    int i = blockIdx.x * blockDim.x + threadIdx.x;   // KPAD * padCols elems
    if (i >= KPAD * padCols) return;
    int r = i / padCols, c = i - r * padCols;
    float v = (r < rows && c < cols) ? src[r * cols + c] : 0.f;
    __nv_bfloat16 hv = __float2bfloat16(v);
    h[i] = hv;
    l[i] = __float2bfloat16(v - __bfloat162float(hv));
}

// ---------------------------------------------------------------------------
// bf16x3 GEMM, fused phases: C = Ah*Bh + Ah*Bl + Al*Bh + bias (fp32 accum).
// Per 32-K chunk: stage Ah/Al/Bh/Bl tiles, issue all 3 products on them.
// Tile 128x64, BK=32, K-loop = 6 chunks, 3-stage cp.async pipeline.
// 256 threads, warps 4(m) x 2(n), warp tile 32x32.
// If C1 != null: columns split into 3 outputs of width splitN (qkv).
// ---------------------------------------------------------------------------
#define GBM 128
#define GBN 64
#define GBK 32
#define ASTR 40       // bf16 units -> 80B row stride  (16B aligned, conflict-free)
#define BSTR 72       // bf16 units -> 144B row stride (16B aligned, conflict-free)
#define NCHUNK (KPAD / GBK)   // 6
#define NSTAGE 3

// byte offsets within one stage (all 16B aligned)
#define OFF_AH 0
#define OFF_AL (GBM * ASTR * 2)                    // 10240
#define OFF_BH (OFF_AL + GBM * ASTR * 2)           // 20480
#define OFF_BL (OFF_BH + GBK * BSTR * 2)           // 25088
#define STAGE_BYTES (OFF_BL + GBK * BSTR * 2)      // 29696
#define SMEM_TOTAL (STAGE_BYTES * NSTAGE)          // 89088

__global__ __launch_bounds__(256, 2) void gemm_bf16x3(
    const __nv_bfloat16* __restrict__ Ah, const __nv_bfloat16* __restrict__ Al,
    const __nv_bfloat16* __restrict__ Bh, const __nv_bfloat16* __restrict__ Bl,
    const float* __restrict__ bias,
    float* __restrict__ C0, float* __restrict__ C1, float* __restrict__ C2,
    int Npad, int Nreal, int splitN)
{
    extern __shared__ char smem[];
    const unsigned sBase = (unsigned)__cvta_generic_to_shared(smem);

    const int tid  = threadIdx.x;
    const int lane = tid & 31;
    const int warp = tid >> 5;
    const int wm   = warp >> 1;          // 0..3 -> m offset *32
    const int wn   = warp & 1;           // 0..1 -> n offset *32
    const int mBase = blockIdx.y * GBM;
    const int nBase = blockIdx.x * GBN;

    float acc[2][4][4];
#pragma unroll
    for (int a = 0; a < 2; a++)
#pragma unroll
        for (int b = 0; b < 4; b++)
#pragma unroll
            for (int c = 0; c < 4; c++) acc[a][b][c] = 0.f;

    // ---- stage loader: chunk c -> stage s (no predicates: all padded) ----
    const int ar = tid >> 2, ac = (tid & 3) * 8;      // A: 2 rows/thread spaced 64
    const int br = tid >> 3, bc = (tid & 7) * 8;      // B: 1 row/thread
    auto loadStage = [&](int c, int s) {
        const int kk = c * GBK;
        const unsigned st = sBase + (unsigned)(s * STAGE_BYTES);
        const __nv_bfloat16* aph = Ah + (size_t)(mBase + ar) * KPAD + kk + ac;
        const __nv_bfloat16* apl = Al + (size_t)(mBase + ar) * KPAD + kk + ac;
        unsigned sa = (unsigned)(ar * ASTR + ac) * 2;
        cp16(st + OFF_AH + sa, aph);
        cp16(st + OFF_AL + sa, apl);
        sa += (unsigned)(64 * ASTR) * 2;
        cp16(st + OFF_AH + sa, aph + (size_t)64 * KPAD);
        cp16(st + OFF_AL + sa, apl + (size_t)64 * KPAD);
        const size_t bo = (size_t)(kk + br) * Npad + nBase + bc;
        const unsigned sb = (unsigned)(br * BSTR + bc) * 2;
        cp16(st + OFF_BH + sb, Bh + bo);
        cp16(st + OFF_BL + sb, Bl + bo);
        cp_commit();
    };

    loadStage(0, 0);
    loadStage(1, 1);

    for (int c = 0; c < NCHUNK; c++) {
        if (c + 1 < NCHUNK) asm volatile("cp.async.wait_group 1;");
        else                asm volatile("cp.async.wait_group 0;");
        __syncthreads();

        if (c + 2 < NCHUNK) loadStage(c + 2, (c + 2) % NSTAGE);

        const unsigned st = sBase + (unsigned)((c % NSTAGE) * STAGE_BYTES);
#pragma unroll
        for (int kf = 0; kf < 2; kf++) {
            unsigned rah[2][4], ral[2][4], rbh[2][4], rbl[2][4];
#pragma unroll
            for (int mf = 0; mf < 2; mf++) {
                unsigned off = (unsigned)((wm * 32 + mf * 16 + (lane & 15)) * ASTR
                                          + kf * 16 + (lane >> 4) * 8) * 2;
                ldsm_x4(rah[mf], st + OFF_AH + off);
                ldsm_x4(ral[mf], st + OFF_AL + off);
            }
#pragma unroll
            for (int nf = 0; nf < 2; nf++) {
                unsigned off = (unsigned)((kf * 16 + (lane & 15)) * BSTR
                                          + wn * 32 + nf * 16 + (lane >> 4) * 8) * 2;
                ldsm_x4_t(rbh[nf], st + OFF_BH + off);
                ldsm_x4_t(rbl[nf], st + OFF_BL + off);
            }
#pragma unroll
            for (int mf = 0; mf < 2; mf++)
#pragma unroll
                for (int nf = 0; nf < 2; nf++) {
                    mma_bf16(acc[mf][nf * 2 + 0], rah[mf], &rbh[nf][0]);
                    mma_bf16(acc[mf][nf * 2 + 1], rah[mf], &rbh[nf][2]);
                    mma_bf16(acc[mf][nf * 2 + 0], rah[mf], &rbl[nf][0]);
                    mma_bf16(acc[mf][nf * 2 + 1], rah[mf], &rbl[nf][2]);
                    mma_bf16(acc[mf][nf * 2 + 0], ral[mf], &rbh[nf][0]);
                    mma_bf16(acc[mf][nf * 2 + 1], ral[mf], &rbh[nf][2]);
                }
        }
        __syncthreads();
    }

    // ---- epilogue ----
#pragma unroll
    for (int mf = 0; mf < 2; mf++)
#pragma unroll
        for (int nf8 = 0; nf8 < 4; nf8++)
#pragma unroll
            for (int i = 0; i < 4; i++) {
                int row = mBase + wm * 32 + mf * 16 + (lane >> 2) + (i >> 1) * 8;
                int col = nBase + wn * 32 + nf8 * 8 + (lane & 3) * 2 + (i & 1);
                if (col < Nreal) {
                    float val = acc[mf][nf8][i] + bias[col];
                    if (C1) {
                        int part = col / splitN;
                        int nc = col - part * splitN;
                        float* Cp = (part == 0) ? C0 : ((part == 1) ? C1 : C2);
                        Cp[(size_t)row * splitN + nc] = val;
                    } else {
                        C0[(size_t)row * Nreal + col] = val;
                    }
                }
            }
}

// ---------------------------------------------------------------------------
// Attention: one warp per (window, head). Writes bf16 hi/lo split directly
// into g_ah/g_al (pad cols 180..191 stay zero from split_a).
// ---------------------------------------------------------------------------
__global__ __launch_bounds__(128) void attn_kernel(
    const float* __restrict__ gq, const float* __restrict__ gk,
    const float* __restrict__ gv, const float* __restrict__ btab,
    const int* __restrict__ ridx,
    __nv_bfloat16* __restrict__ outh, __nv_bfloat16* __restrict__ outl)
{
    __shared__ float sbias[NHEADS * 256];    // [h][r][c]
    __shared__ float sqT[4][HD_ * TOK];      // q transposed: [d][n]
    __shared__ float sk[4][TOK * HD_];       // [n][d]
    __shared__ float sv[4][TOK * HD_];       // [n][d]
    __shared__ float sPT[4][TOK * TOK];      // P transposed: [c][r]

    const int tid = threadIdx.x;
    for (int i = tid; i < NHEADS * 256; i += 128) {
        int h = i >> 8, rc = i & 255;
        sbias[i] = btab[ridx[rc] * NHEADS + h];
    }
    __syncthreads();

    const int warp = tid >> 5, lane = tid & 31;
    const int task = blockIdx.x * 4 + warp;
    const int b = task / NHEADS;
    const int h = task - b * NHEADS;
    const float scale = 0.18257418583505537f;  // 30^-0.5

    float* q = sqT[warp];
    float* k = sk[warp];
    float* v = sv[warp];
    float* P = sPT[warp];

    const size_t base = (size_t)b * TOK * DIM_ + h * HD_;
    for (int i = lane; i < TOK * HD_; i += 32) {
        int n = i / HD_, d = i - n * HD_;
        size_t g = base + (size_t)n * DIM_ + d;
        q[d * TOK + n] = gq[g] * scale;
        k[i] = gk[g];
        v[i] = gv[g];
    }
    __syncwarp();

    const int r  = lane >> 1;
    const int cb = (lane & 1) * 8;
    float s[8];
#pragma unroll
    for (int c = 0; c < 8; c++) {
        float a = sbias[h * 256 + r * 16 + cb + c];
#pragma unroll
        for (int d = 0; d < HD_; d++)
            a = fmaf(q[d * TOK + r], k[(cb + c) * HD_ + d], a);
        s[c] = a;
    }
    float mx = s[0];
#pragma unroll
    for (int c = 1; c < 8; c++) mx = fmaxf(mx, s[c]);
    mx = fmaxf(mx, __shfl_xor_sync(0xffffffffu, mx, 1));
    float sum = 0.f;
#pragma unroll
    for (int c = 0; c < 8; c++) { s[c] = __expf(s[c] - mx); sum += s[c]; }
    sum += __shfl_xor_sync(0xffffffffu, sum, 1);
    const float inv = 1.f / sum;
#pragma unroll
    for (int c = 0; c < 8; c++) P[(cb + c) * TOK + r] = s[c] * inv;
    __syncwarp();

    const int cb2 = (lane & 1) * 15;
    float o[15];
#pragma unroll
    for (int c = 0; c < 15; c++) o[c] = 0.f;
#pragma unroll
    for (int m = 0; m < TOK; m++) {
        float p = P[m * TOK + r];
#pragma unroll
        for (int c = 0; c < 15; c++)
            o[c] = fmaf(p, v[m * HD_ + cb2 + c], o[c]);
    }
    size_t ob = (size_t)b * TOK * KPAD + (size_t)r * KPAD + h * HD_ + cb2;
#pragma unroll
    for (int c = 0; c < 15; c++) {
        __nv_bfloat16 hv = __float2bfloat16(o[c]);
        outh[ob + c] = hv;
        outl[ob + c] = __float2bfloat16(o[c] - __bfloat162float(hv));
    }
}

// ---------------------------------------------------------------------------
extern "C" void kernel_launch(void* const* d_in, const int* in_sizes, int n_in,
                              void* d_out, int out_size)
{
    const float* x      = (const float*)d_in[0];
    const float* w_qkv  = (const float*)d_in[1];
    const float* b_qkv  = (const float*)d_in[2];
    const float* w_proj = (const float*)d_in[3];
    const float* b_proj = (const float*)d_in[4];
    const float* btab   = (const float*)d_in[5];
    const int*   ridx   = (const int*)d_in[6];
    float*       out    = (float*)d_out;

    float *gq, *gk, *gv;
    __nv_bfloat16 *ah, *al, *wqh, *wql, *wph, *wpl;
    cudaGetSymbolAddress((void**)&gq,  g_q);
    cudaGetSymbolAddress((void**)&gk,  g_k);
    cudaGetSymbolAddress((void**)&gv,  g_v);
    cudaGetSymbolAddress((void**)&ah,  g_ah);
    cudaGetSymbolAddress((void**)&al,  g_al);
    cudaGetSymbolAddress((void**)&wqh, g_wqh);
    cudaGetSymbolAddress((void**)&wql, g_wql);
    cudaGetSymbolAddress((void**)&wph, g_wph);
    cudaGetSymbolAddress((void**)&wpl, g_wpl);

    static bool attr_set = false;
    if (!attr_set) {
        cudaFuncSetAttribute(gemm_bf16x3,
                             cudaFuncAttributeMaxDynamicSharedMemorySize, SMEM_TOTAL);
        attr_set = true;
    }

    // 0) splits
    split_a_kernel<<<NROWS, KPAD>>>(x, ah, al);
    split_w_kernel<<<(KPAD * NQKV_PAD + 255) / 256, 256>>>(w_qkv, DIM_, NQKV, wqh, wql, NQKV_PAD);
    split_w_kernel<<<(KPAD * NPROJ_PAD + 255) / 256, 256>>>(w_proj, DIM_, DIM_, wph, wpl, NPROJ_PAD);

    // 1) qkv = x @ w_qkv + b_qkv  (bf16x3 fused, split into q/k/v fp32)
    dim3 g1(NQKV_PAD / GBN, NROWS / GBM);    // (9, 8192)
    gemm_bf16x3<<<g1, 256, SMEM_TOTAL>>>(ah, al, wqh, wql, b_qkv, gq, gk, gv,
                                         NQKV_PAD, NQKV, DIM_);

    // 2) windowed attention; emits bf16 hi/lo into ah/al (pads still zero)
    attn_kernel<<<(NWIN * NHEADS) / 4, 128>>>(gq, gk, gv, btab, ridx, ah, al);

    // 3) out = att @ w_proj + b_proj  (bf16x3 fused)
    dim3 g3(NPROJ_PAD / GBN, NROWS / GBM);   // (3, 8192)
    gemm_bf16x3<<<g3, 256, SMEM_TOTAL>>>(ah, al, wph, wpl, b_proj, out, nullptr, nullptr,
                                         NPROJ_PAD, DIM_, DIM_);
}